// round 6
// baseline (speedup 1.0000x reference)
#include <cuda_runtime.h>
#include <math.h>
#include <stdint.h>

#define NNODE 16384
#define DCAT  1024
#define DHEAD 512
#define MAXE  (524288 + NNODE)

// ---------------- scratch (device globals; allocation-free contract) -------
__device__ float  g_xh[NNODE * DCAT];     // x @ W
__device__ float  g_h[NNODE * DCAT];      // aggregated + bias + relu
__device__ float  g_h128[NNODE * 128];
__device__ float  g_h64[NNODE * 64];
__device__ float4 g_hp[NNODE];            // (h3.x, h3.y, h3.z, sq)
__device__ float  g_asrc[NNODE * 2];
__device__ float  g_adst[NNODE * 2];
__device__ float  g_z[NNODE * 2];
__device__ int    g_deg[NNODE];
__device__ int    g_cursor[NNODE];
__device__ int    g_rowptr[NNODE + 1];
__device__ int    g_csr_src[MAXE];
__device__ float2 g_csr_alpha[MAXE];

// ---------------- tf32 helpers ---------------------------------------------
__device__ __forceinline__ uint32_t f2tf32(float f)
{
    uint32_t u;
    asm("cvt.rna.tf32.f32 %0, %1;" : "=r"(u) : "f"(f));
    return u;
}

__device__ __forceinline__ float4 cvt4(float4 v)
{
    float4 w;
    w.x = __uint_as_float(f2tf32(v.x));
    w.y = __uint_as_float(f2tf32(v.y));
    w.z = __uint_as_float(f2tf32(v.z));
    w.w = __uint_as_float(f2tf32(v.w));
    return w;
}

__device__ __forceinline__ void mma_tf32(float& c0, float& c1, float& c2, float& c3,
                                         uint32_t a0, uint32_t a1, uint32_t a2, uint32_t a3,
                                         uint32_t b0, uint32_t b1)
{
    asm volatile(
        "mma.sync.aligned.m16n8k8.row.col.f32.tf32.tf32.f32 "
        "{%0,%1,%2,%3}, {%4,%5,%6,%7}, {%8,%9}, {%0,%1,%2,%3};"
        : "+f"(c0), "+f"(c1), "+f"(c2), "+f"(c3)
        : "r"(a0), "r"(a1), "r"(a2), "r"(a3), "r"(b0), "r"(b1));
}

// ---------------- tf32 tensor-core GEMM, register-prefetch pipelined -------
// C = A[M,K] @ B[K,N] (+bias)(+relu). BM=128, BN=64, BK=16, 256 threads =
// 8 warps (4 m x 2 n), 32x32 per warp. M%128==0, N%64==0, K%16==0.
// MODE selects A/C from device globals at compile time:
//   MODE 0: A = Aarg (input x), C = g_xh
//   MODE 1: A = g_h,            C = g_h128
//   MODE 2: A = g_h128,         C = g_h64
template <int MODE, bool RELU>
__global__ __launch_bounds__(256)
void tf32gemm(int M, int N, int K,
              const float* __restrict__ Aarg, const float* __restrict__ B,
              const float* __restrict__ bias)
{
    const float* __restrict__ A =
        (MODE == 0) ? Aarg : (MODE == 1) ? (const float*)g_h : (const float*)g_h128;
    float* __restrict__ C =
        (MODE == 0) ? (float*)g_xh : (MODE == 1) ? (float*)g_h128 : (float*)g_h64;

    constexpr int BM = 128, BN = 64, BK = 16;
    __shared__ float Am[BM][BK + 4];   // m-major, stride 20 (conflict-free frag LDS)
    __shared__ float Bs[BK][BN + 8];   // k-major, stride 72 (conflict-free frag LDS)

    const int tid   = threadIdx.x;
    const int lane  = tid & 31;
    const int wid   = tid >> 5;
    const int g     = lane >> 2;       // 0..7
    const int tig   = lane & 3;        // 0..3
    const int warpM = wid & 3;         // 0..3  (32 rows each)
    const int warpN = wid >> 2;        // 0..1  (32 cols each)
    const int m0    = blockIdx.y * BM;
    const int n0    = blockIdx.x * BN;

    float c[2][4][4];
#pragma unroll
    for (int mt = 0; mt < 2; mt++)
#pragma unroll
        for (int nt = 0; nt < 4; nt++)
#pragma unroll
            for (int i = 0; i < 4; i++) c[mt][nt][i] = 0.f;

    const int aRow = tid >> 2;         // 0..63
    const int aK   = (tid & 3) * 4;    // 0,4,8,12
    const int bK   = tid >> 4;         // 0..15
    const int bN   = (tid & 15) * 4;   // 0..60

    const float* Ald = A + (size_t)(m0 + aRow) * K + aK;
    const float* Bld = B + (size_t)bK * N + n0 + bN;

    // prologue: prefetch tile 0 into registers
    float4 av0 = *(const float4*)(Ald);
    float4 av1 = *(const float4*)(Ald + (size_t)64 * K);
    float4 bv  = *(const float4*)(Bld);

    for (int k0 = 0; k0 < K; k0 += BK) {
        // commit prefetched tile to smem (convert to tf32 on store)
        *(float4*)&Am[aRow][aK]      = cvt4(av0);
        *(float4*)&Am[64 + aRow][aK] = cvt4(av1);
        *(float4*)&Bs[bK][bN]        = cvt4(bv);
        __syncthreads();

        // issue next tile's global loads early; they drain behind the MMAs
        if (k0 + BK < K) {
            av0 = *(const float4*)(Ald + k0 + BK);
            av1 = *(const float4*)(Ald + (size_t)64 * K + k0 + BK);
            bv  = *(const float4*)(Bld + (size_t)(k0 + BK) * N);
        }

#pragma unroll
        for (int kk = 0; kk < BK; kk += 8) {
            uint32_t a[2][4];
#pragma unroll
            for (int mt = 0; mt < 2; mt++) {
                int mm = warpM * 32 + mt * 16 + g;
                a[mt][0] = __float_as_uint(Am[mm][kk + tig]);
                a[mt][1] = __float_as_uint(Am[mm + 8][kk + tig]);
                a[mt][2] = __float_as_uint(Am[mm][kk + tig + 4]);
                a[mt][3] = __float_as_uint(Am[mm + 8][kk + tig + 4]);
            }
            uint32_t b[4][2];
#pragma unroll
            for (int nt = 0; nt < 4; nt++) {
                int nn = warpN * 32 + nt * 8 + g;
                b[nt][0] = __float_as_uint(Bs[kk + tig][nn]);
                b[nt][1] = __float_as_uint(Bs[kk + tig + 4][nn]);
            }
#pragma unroll
            for (int mt = 0; mt < 2; mt++)
#pragma unroll
                for (int nt = 0; nt < 4; nt++)
                    mma_tf32(c[mt][nt][0], c[mt][nt][1], c[mt][nt][2], c[mt][nt][3],
                             a[mt][0], a[mt][1], a[mt][2], a[mt][3],
                             b[nt][0], b[nt][1]);
        }
        __syncthreads();
    }

    // --- epilogue: bias + relu + float2 stores ---
#pragma unroll
    for (int mt = 0; mt < 2; mt++) {
        int r0 = m0 + warpM * 32 + mt * 16 + g;
#pragma unroll
        for (int nt = 0; nt < 4; nt++) {
            int cc = n0 + warpN * 32 + nt * 8 + 2 * tig;
            float b0 = 0.f, b1 = 0.f;
            if (bias) { b0 = bias[cc]; b1 = bias[cc + 1]; }
            float v00 = c[mt][nt][0] + b0, v01 = c[mt][nt][1] + b1;
            float v10 = c[mt][nt][2] + b0, v11 = c[mt][nt][3] + b1;
            if (RELU) {
                v00 = fmaxf(v00, 0.f); v01 = fmaxf(v01, 0.f);
                v10 = fmaxf(v10, 0.f); v11 = fmaxf(v11, 0.f);
            }
            *(float2*)&C[(size_t)r0 * N + cc]       = make_float2(v00, v01);
            *(float2*)&C[(size_t)(r0 + 8) * N + cc] = make_float2(v10, v11);
        }
    }
}

// ---------------- attention scores: a_src/a_dst [N,2] ----------------------
__global__ __launch_bounds__(128)
void attn_scores(const float* __restrict__ att_src,
                 const float* __restrict__ att_dst)
{
    int n = blockIdx.x;
    int w = threadIdx.x >> 5;      // 0..3
    int lane = threadIdx.x & 31;
    int h = w & 1;
    const float* row = g_xh + (size_t)n * DCAT + h * DHEAD;
    const float* att = ((w < 2) ? att_src : att_dst) + h * DHEAD;
    float s = 0.f;
    for (int i = lane; i < DHEAD; i += 32) s += row[i] * att[i];
#pragma unroll
    for (int o = 16; o > 0; o >>= 1) s += __shfl_down_sync(0xffffffffu, s, o);
    if (lane == 0) {
        float* out = (w < 2) ? g_asrc : g_adst;
        out[n * 2 + h] = s;
    }
}

// ---------------- zero init (z, deg) ---------------------------------------
__global__ void zero_init_kernel()
{
    int i = blockIdx.x * blockDim.x + threadIdx.x;
    if (i < NNODE * 2) g_z[i] = 0.f;
    if (i < NNODE) g_deg[i] = 0;
}

__device__ __forceinline__ float leaky(float x) { return x > 0.f ? x : 0.2f * x; }

// edge_index is int32; mask is a no-op on valid data but converts surprises
// into wrong values instead of device traps.
__device__ __forceinline__ void edge_sd(const int* __restrict__ ei, int e,
                                        int E, int& s, int& d)
{
    if (e < E) {
        s = ei[e] & (NNODE - 1);
        d = ei[E + e] & (NNODE - 1);
    } else {
        s = d = e - E;   // self-loop
    }
}

// ---------------- edge pass 1: softmax denominator + degree ----------------
__global__ __launch_bounds__(256)
void edge_pass1(const int* __restrict__ ei, int E, int Etot)
{
    int e = blockIdx.x * blockDim.x + threadIdx.x;
    if (e >= Etot) return;
    int s, d;
    edge_sd(ei, e, E, s, d);
#pragma unroll
    for (int h = 0; h < 2; h++) {
        float l = leaky(g_asrc[2 * s + h] + g_adst[2 * d + h]);
        atomicAdd(&g_z[2 * d + h], expf(l));
    }
    atomicAdd(&g_deg[d], 1);
}

// ---------------- exclusive scan of degrees --> rowptr, cursor -------------
__global__ __launch_bounds__(512)
void scan_kernel()
{
    __shared__ int sums[512];
    int t = threadIdx.x;
    int base = t * 32;
    int local[32];
    int s = 0;
#pragma unroll
    for (int i = 0; i < 32; i++) { local[i] = s; s += g_deg[base + i]; }
    sums[t] = s;
    __syncthreads();
    for (int off = 1; off < 512; off <<= 1) {
        int v = (t >= off) ? sums[t - off] : 0;
        __syncthreads();
        if (t >= off) sums[t] += v;
        __syncthreads();
    }
    int prefix = (t == 0) ? 0 : sums[t - 1];
#pragma unroll
    for (int i = 0; i < 32; i++) {
        g_rowptr[base + i] = prefix + local[i];
        g_cursor[base + i] = prefix + local[i];
    }
    if (t == 511) g_rowptr[NNODE] = sums[511];
}

// ---------------- edge pass 2: scatter CSR entries (src, alpha) ------------
__global__ __launch_bounds__(256)
void edge_scatter(const int* __restrict__ ei, int E, int Etot)
{
    int e = blockIdx.x * blockDim.x + threadIdx.x;
    if (e >= Etot) return;
    int s, d;
    edge_sd(ei, e, E, s, d);
    int pos = atomicAdd(&g_cursor[d], 1);
    float2 al;
    {
        float l0 = leaky(g_asrc[2 * s + 0] + g_adst[2 * d + 0]);
        float l1 = leaky(g_asrc[2 * s + 1] + g_adst[2 * d + 1]);
        al.x = expf(l0) / fmaxf(g_z[2 * d + 0], 1e-16f);
        al.y = expf(l1) / fmaxf(g_z[2 * d + 1], 1e-16f);
    }
    g_csr_src[pos] = s;
    g_csr_alpha[pos] = al;
}

// ---------------- aggregation (atomic-free) + bias + relu ------------------
__global__ __launch_bounds__(256)
void aggregate_kernel(const float* __restrict__ bias)
{
    int d = blockIdx.x;
    int c = threadIdx.x * 4;             // 0..1020
    bool head1 = (c >= DHEAD);
    int beg = g_rowptr[d], end = g_rowptr[d + 1];
    float4 acc = make_float4(0.f, 0.f, 0.f, 0.f);
    for (int i = beg; i < end; i++) {
        int s = g_csr_src[i];
        float2 al = g_csr_alpha[i];
        float a = head1 ? al.y : al.x;
        float4 v = *(const float4*)(g_xh + (size_t)s * DCAT + c);
        acc.x += a * v.x; acc.y += a * v.y; acc.z += a * v.z; acc.w += a * v.w;
    }
    float4 b = *(const float4*)(bias + c);
    acc.x = fmaxf(acc.x + b.x, 0.f);
    acc.y = fmaxf(acc.y + b.y, 0.f);
    acc.z = fmaxf(acc.z + b.z, 0.f);
    acc.w = fmaxf(acc.w + b.w, 0.f);
    *(float4*)(g_h + (size_t)d * DCAT + c) = acc;
}

// ---------------- head: h3 = h64 @ W2 + b2, plus sq ------------------------
__global__ __launch_bounds__(256)
void head_kernel(const float* __restrict__ W2, const float* __restrict__ b2)
{
    int n = blockIdx.x * blockDim.x + threadIdx.x;
    if (n >= NNODE) return;
    float a0 = b2[0], a1 = b2[1], a2 = b2[2];
    const float* row = g_h64 + (size_t)n * 64;
#pragma unroll 8
    for (int k = 0; k < 64; k++) {
        float v = row[k];
        a0 = fmaf(v, W2[k * 3 + 0], a0);
        a1 = fmaf(v, W2[k * 3 + 1], a1);
        a2 = fmaf(v, W2[k * 3 + 2], a2);
    }
    float sq = fmaf(a2, a2, fmaf(a1, a1, a0 * a0));
    g_hp[n] = make_float4(a0, a1, a2, sq);
}

// ---------------- cdist: out[i][j] = ||h_i - h_j||, 4 j per thread ---------
__global__ __launch_bounds__(256)
void cdist_kernel(float* __restrict__ out)
{
    int j = (blockIdx.x * 256 + threadIdx.x) * 4;    // 0..16380
    int i = blockIdx.y;
    float4 hi = g_hp[i];
    float4 r;
    // dot uses the exact fmaf chain used for sq => diagonal is exactly 0
    {
        float4 hj = g_hp[j + 0];
        float dot = fmaf(hi.z, hj.z, fmaf(hi.y, hj.y, hi.x * hj.x));
        float d2 = fmaxf((hi.w + hj.w) - 2.f * dot, 0.f);
        r.x = (d2 > 0.f) ? sqrtf(d2) : 0.f;
    }
    {
        float4 hj = g_hp[j + 1];
        float dot = fmaf(hi.z, hj.z, fmaf(hi.y, hj.y, hi.x * hj.x));
        float d2 = fmaxf((hi.w + hj.w) - 2.f * dot, 0.f);
        r.y = (d2 > 0.f) ? sqrtf(d2) : 0.f;
    }
    {
        float4 hj = g_hp[j + 2];
        float dot = fmaf(hi.z, hj.z, fmaf(hi.y, hj.y, hi.x * hj.x));
        float d2 = fmaxf((hi.w + hj.w) - 2.f * dot, 0.f);
        r.z = (d2 > 0.f) ? sqrtf(d2) : 0.f;
    }
    {
        float4 hj = g_hp[j + 3];
        float dot = fmaf(hi.z, hj.z, fmaf(hi.y, hj.y, hi.x * hj.x));
        float d2 = fmaxf((hi.w + hj.w) - 2.f * dot, 0.f);
        r.w = (d2 > 0.f) ? sqrtf(d2) : 0.f;
    }
    *(float4*)&out[(size_t)i * NNODE + j] = r;
}

// ---------------------------------------------------------------------------
extern "C" void kernel_launch(void* const* d_in, const int* in_sizes, int n_in,
                              void* d_out, int out_size)
{
    const float* x       = (const float*)d_in[0];
    const int*   ei      = (const int*)d_in[1];      // int32 (JAX default)
    const float* W       = (const float*)d_in[2];
    const float* att_src = (const float*)d_in[3];
    const float* att_dst = (const float*)d_in[4];
    const float* bias    = (const float*)d_in[5];
    const float* Wa      = (const float*)d_in[6];
    const float* ba      = (const float*)d_in[7];
    const float* W1      = (const float*)d_in[8];
    const float* b1      = (const float*)d_in[9];
    const float* W2      = (const float*)d_in[10];
    const float* b2      = (const float*)d_in[11];
    float* out = (float*)d_out;

    int E = in_sizes[1] / 2;
    int Etot = E + NNODE;

    // 1) xh = x @ W   [16384,1024] K=512  (tensor cores, tf32, pipelined)
    tf32gemm<0, false><<<dim3(DCAT / 64, NNODE / 128), 256>>>(
        NNODE, DCAT, 512, x, W, nullptr);

    // 2) attention scores
    attn_scores<<<NNODE, 128>>>(att_src, att_dst);

    // 3) zero z/deg
    zero_init_kernel<<<(NNODE * 2 + 255) / 256, 256>>>();

    // 4) softmax denominator + degree histogram
    edge_pass1<<<(Etot + 255) / 256, 256>>>(ei, E, Etot);

    // 5) scan degrees -> rowptr/cursor
    scan_kernel<<<1, 512>>>();

    // 6) scatter CSR (src, alpha)
    edge_scatter<<<(Etot + 255) / 256, 256>>>(ei, E, Etot);

    // 7) aggregate messages (atomic-free) + bias + relu -> h
    aggregate_kernel<<<NNODE, 256>>>(bias);

    // 8) h128 = relu(h @ Wa + ba)   K=1024, N=128
    tf32gemm<1, true><<<dim3(2, NNODE / 128), 256>>>(
        NNODE, 128, DCAT, nullptr, Wa, ba);

    // 9) h64 = relu(h128 @ W1 + b1)  K=128, N=64
    tf32gemm<2, true><<<dim3(1, NNODE / 128), 256>>>(
        NNODE, 64, 128, nullptr, W1, b1);

    // 10) h3 + sq
    head_kernel<<<NNODE / 256, 256>>>(W2, b2);

    // 11) cdist (float4 stores)
    cdist_kernel<<<dim3(NNODE / 1024, NNODE), 256>>>(out);

    (void)n_in; (void)out_size;
}

// round 7
// speedup vs baseline: 1.0398x; 1.0398x over previous
#include <cuda_runtime.h>
#include <math.h>
#include <stdint.h>

#define NNODE 16384
#define DCAT  1024
#define DHEAD 512
#define MAXE  (524288 + NNODE)

// ---------------- scratch (device globals; allocation-free contract) -------
__device__ float  g_xh[NNODE * DCAT];     // x @ W
__device__ float  g_h[NNODE * DCAT];      // aggregated + bias + relu
__device__ float  g_h128[NNODE * 128];
__device__ float  g_h64[NNODE * 64];
__device__ float4 g_hp[NNODE];            // (h3.x, h3.y, h3.z, sq)
__device__ float  g_asrc[NNODE * 2];
__device__ float  g_adst[NNODE * 2];
__device__ float  g_z[NNODE * 2];
__device__ int    g_deg[NNODE];
__device__ int    g_cursor[NNODE];
__device__ int    g_rowptr[NNODE + 1];
__device__ int    g_csr_src[MAXE];
__device__ float2 g_csr_alpha[MAXE];

// ---------------- tf32 / cp.async helpers ----------------------------------
__device__ __forceinline__ uint32_t f2tf32(float f)
{
    uint32_t u;
    asm("cvt.rna.tf32.f32 %0, %1;" : "=r"(u) : "f"(f));
    return u;
}

__device__ __forceinline__ void cpa16(void* smem_dst, const void* gsrc)
{
    uint32_t s = (uint32_t)__cvta_generic_to_shared(smem_dst);
    asm volatile("cp.async.cg.shared.global [%0], [%1], 16;" :: "r"(s), "l"(gsrc));
}
__device__ __forceinline__ void cp_commit()
{
    asm volatile("cp.async.commit_group;" ::: "memory");
}
__device__ __forceinline__ void cp_wait0()
{
    asm volatile("cp.async.wait_group 0;" ::: "memory");
}

__device__ __forceinline__ void mma_tf32(float& c0, float& c1, float& c2, float& c3,
                                         uint32_t a0, uint32_t a1, uint32_t a2, uint32_t a3,
                                         uint32_t b0, uint32_t b1)
{
    asm volatile(
        "mma.sync.aligned.m16n8k8.row.col.f32.tf32.tf32.f32 "
        "{%0,%1,%2,%3}, {%4,%5,%6,%7}, {%8,%9}, {%0,%1,%2,%3};"
        : "+f"(c0), "+f"(c1), "+f"(c2), "+f"(c3)
        : "r"(a0), "r"(a1), "r"(a2), "r"(a3), "r"(b0), "r"(b1));
}

// ---------------- tf32 tensor-core GEMM, cp.async double-buffered ----------
// C = A[M,K] @ B[K,N] (+bias)(+relu). BM=128, BN=64, BK=16, 256 threads =
// 8 warps (4 m x 2 n), 32x32 per warp. M%128==0, N%64==0, K%16==0.
// Raw fp32 staged to smem via LDGSTS (bypasses RF); cvt.rna.tf32 applied on
// the fragment registers after LDS — numerically identical to converting
// before the STS. MODE selects A/C from device globals at compile time:
//   MODE 0: A = Aarg (input x), C = g_xh
//   MODE 1: A = g_h,            C = g_h128
//   MODE 2: A = g_h128,         C = g_h64
template <int MODE, bool RELU>
__global__ __launch_bounds__(256)
void tf32gemm(int M, int N, int K,
              const float* __restrict__ Aarg, const float* __restrict__ B,
              const float* __restrict__ bias)
{
    const float* __restrict__ A =
        (MODE == 0) ? Aarg : (MODE == 1) ? (const float*)g_h : (const float*)g_h128;
    float* __restrict__ C =
        (MODE == 0) ? (float*)g_xh : (MODE == 1) ? (float*)g_h128 : (float*)g_h64;

    constexpr int BM = 128, BN = 64, BK = 16;
    __shared__ float Am[2][BM][BK + 4];   // m-major, stride 20 (80B rows, 16B-aligned)
    __shared__ float Bs[2][BK][BN + 8];   // k-major, stride 72 (288B rows, 16B-aligned)

    const int tid   = threadIdx.x;
    const int lane  = tid & 31;
    const int wid   = tid >> 5;
    const int g     = lane >> 2;       // 0..7
    const int tig   = lane & 3;        // 0..3
    const int warpM = wid & 3;         // 0..3  (32 rows each)
    const int warpN = wid >> 2;        // 0..1  (32 cols each)
    const int m0    = blockIdx.y * BM;
    const int n0    = blockIdx.x * BN;

    float c[2][4][4];
#pragma unroll
    for (int mt = 0; mt < 2; mt++)
#pragma unroll
        for (int nt = 0; nt < 4; nt++)
#pragma unroll
            for (int i = 0; i < 4; i++) c[mt][nt][i] = 0.f;

    const int aRow = tid >> 2;         // 0..63
    const int aK   = (tid & 3) * 4;    // 0,4,8,12
    const int bK   = tid >> 4;         // 0..15
    const int bN   = (tid & 15) * 4;   // 0..60

    const float* Ald = A + (size_t)(m0 + aRow) * K + aK;
    const float* Bld = B + (size_t)bK * N + n0 + bN;

    // prologue: stage tile 0 into buffer 0
    cpa16(&Am[0][aRow][aK],      Ald);
    cpa16(&Am[0][64 + aRow][aK], Ald + (size_t)64 * K);
    cpa16(&Bs[0][bK][bN],        Bld);
    cp_commit();

    const int nTiles = K / BK;
    for (int t = 0; t < nTiles; t++) {
        const int cur = t & 1;
        cp_wait0();
        __syncthreads();                 // tile t resident in buf[cur]

        if (t + 1 < nTiles) {            // stage tile t+1 into the other buffer
            int k1 = (t + 1) * BK;
            cpa16(&Am[cur ^ 1][aRow][aK],      Ald + k1);
            cpa16(&Am[cur ^ 1][64 + aRow][aK], Ald + (size_t)64 * K + k1);
            cpa16(&Bs[cur ^ 1][bK][bN],        Bld + (size_t)k1 * N);
            cp_commit();
        }

#pragma unroll
        for (int kk = 0; kk < BK; kk += 8) {
            uint32_t a[2][4];
#pragma unroll
            for (int mt = 0; mt < 2; mt++) {
                int mm = warpM * 32 + mt * 16 + g;
                a[mt][0] = f2tf32(Am[cur][mm][kk + tig]);
                a[mt][1] = f2tf32(Am[cur][mm + 8][kk + tig]);
                a[mt][2] = f2tf32(Am[cur][mm][kk + tig + 4]);
                a[mt][3] = f2tf32(Am[cur][mm + 8][kk + tig + 4]);
            }
            uint32_t b[4][2];
#pragma unroll
            for (int nt = 0; nt < 4; nt++) {
                int nn = warpN * 32 + nt * 8 + g;
                b[nt][0] = f2tf32(Bs[cur][kk + tig][nn]);
                b[nt][1] = f2tf32(Bs[cur][kk + tig + 4][nn]);
            }
#pragma unroll
            for (int mt = 0; mt < 2; mt++)
#pragma unroll
                for (int nt = 0; nt < 4; nt++)
                    mma_tf32(c[mt][nt][0], c[mt][nt][1], c[mt][nt][2], c[mt][nt][3],
                             a[mt][0], a[mt][1], a[mt][2], a[mt][3],
                             b[nt][0], b[nt][1]);
        }
        __syncthreads();                 // all reads of buf[cur] done before it
                                         // is overwritten at t+2
    }

    // --- epilogue: bias + relu + float2 stores ---
#pragma unroll
    for (int mt = 0; mt < 2; mt++) {
        int r0 = m0 + warpM * 32 + mt * 16 + g;
#pragma unroll
        for (int nt = 0; nt < 4; nt++) {
            int cc = n0 + warpN * 32 + nt * 8 + 2 * tig;
            float b0 = 0.f, b1 = 0.f;
            if (bias) { b0 = bias[cc]; b1 = bias[cc + 1]; }
            float v00 = c[mt][nt][0] + b0, v01 = c[mt][nt][1] + b1;
            float v10 = c[mt][nt][2] + b0, v11 = c[mt][nt][3] + b1;
            if (RELU) {
                v00 = fmaxf(v00, 0.f); v01 = fmaxf(v01, 0.f);
                v10 = fmaxf(v10, 0.f); v11 = fmaxf(v11, 0.f);
            }
            *(float2*)&C[(size_t)r0 * N + cc]       = make_float2(v00, v01);
            *(float2*)&C[(size_t)(r0 + 8) * N + cc] = make_float2(v10, v11);
        }
    }
}

// ---------------- attention scores: a_src/a_dst [N,2] ----------------------
__global__ __launch_bounds__(128)
void attn_scores(const float* __restrict__ att_src,
                 const float* __restrict__ att_dst)
{
    int n = blockIdx.x;
    int w = threadIdx.x >> 5;      // 0..3
    int lane = threadIdx.x & 31;
    int h = w & 1;
    const float* row = g_xh + (size_t)n * DCAT + h * DHEAD;
    const float* att = ((w < 2) ? att_src : att_dst) + h * DHEAD;
    float s = 0.f;
    for (int i = lane; i < DHEAD; i += 32) s += row[i] * att[i];
#pragma unroll
    for (int o = 16; o > 0; o >>= 1) s += __shfl_down_sync(0xffffffffu, s, o);
    if (lane == 0) {
        float* out = (w < 2) ? g_asrc : g_adst;
        out[n * 2 + h] = s;
    }
}

// ---------------- zero init (z, deg) ---------------------------------------
__global__ void zero_init_kernel()
{
    int i = blockIdx.x * blockDim.x + threadIdx.x;
    if (i < NNODE * 2) g_z[i] = 0.f;
    if (i < NNODE) g_deg[i] = 0;
}

__device__ __forceinline__ float leaky(float x) { return x > 0.f ? x : 0.2f * x; }

// edge_index is int32; mask is a no-op on valid data but converts surprises
// into wrong values instead of device traps.
__device__ __forceinline__ void edge_sd(const int* __restrict__ ei, int e,
                                        int E, int& s, int& d)
{
    if (e < E) {
        s = ei[e] & (NNODE - 1);
        d = ei[E + e] & (NNODE - 1);
    } else {
        s = d = e - E;   // self-loop
    }
}

// ---------------- edge pass 1: softmax denominator + degree ----------------
__global__ __launch_bounds__(256)
void edge_pass1(const int* __restrict__ ei, int E, int Etot)
{
    int e = blockIdx.x * blockDim.x + threadIdx.x;
    if (e >= Etot) return;
    int s, d;
    edge_sd(ei, e, E, s, d);
#pragma unroll
    for (int h = 0; h < 2; h++) {
        float l = leaky(g_asrc[2 * s + h] + g_adst[2 * d + h]);
        atomicAdd(&g_z[2 * d + h], expf(l));
    }
    atomicAdd(&g_deg[d], 1);
}

// ---------------- exclusive scan of degrees --> rowptr, cursor -------------
__global__ __launch_bounds__(512)
void scan_kernel()
{
    __shared__ int sums[512];
    int t = threadIdx.x;
    int base = t * 32;
    int local[32];
    int s = 0;
#pragma unroll
    for (int i = 0; i < 32; i++) { local[i] = s; s += g_deg[base + i]; }
    sums[t] = s;
    __syncthreads();
    for (int off = 1; off < 512; off <<= 1) {
        int v = (t >= off) ? sums[t - off] : 0;
        __syncthreads();
        if (t >= off) sums[t] += v;
        __syncthreads();
    }
    int prefix = (t == 0) ? 0 : sums[t - 1];
#pragma unroll
    for (int i = 0; i < 32; i++) {
        g_rowptr[base + i] = prefix + local[i];
        g_cursor[base + i] = prefix + local[i];
    }
    if (t == 511) g_rowptr[NNODE] = sums[511];
}

// ---------------- edge pass 2: scatter CSR entries (src, alpha) ------------
__global__ __launch_bounds__(256)
void edge_scatter(const int* __restrict__ ei, int E, int Etot)
{
    int e = blockIdx.x * blockDim.x + threadIdx.x;
    if (e >= Etot) return;
    int s, d;
    edge_sd(ei, e, E, s, d);
    int pos = atomicAdd(&g_cursor[d], 1);
    float2 al;
    {
        float l0 = leaky(g_asrc[2 * s + 0] + g_adst[2 * d + 0]);
        float l1 = leaky(g_asrc[2 * s + 1] + g_adst[2 * d + 1]);
        al.x = expf(l0) / fmaxf(g_z[2 * d + 0], 1e-16f);
        al.y = expf(l1) / fmaxf(g_z[2 * d + 1], 1e-16f);
    }
    g_csr_src[pos] = s;
    g_csr_alpha[pos] = al;
}

// ---------------- aggregation (atomic-free) + bias + relu ------------------
__global__ __launch_bounds__(256)
void aggregate_kernel(const float* __restrict__ bias)
{
    int d = blockIdx.x;
    int c = threadIdx.x * 4;             // 0..1020
    bool head1 = (c >= DHEAD);
    int beg = g_rowptr[d], end = g_rowptr[d + 1];
    float4 acc = make_float4(0.f, 0.f, 0.f, 0.f);
    for (int i = beg; i < end; i++) {
        int s = g_csr_src[i];
        float2 al = g_csr_alpha[i];
        float a = head1 ? al.y : al.x;
        float4 v = *(const float4*)(g_xh + (size_t)s * DCAT + c);
        acc.x += a * v.x; acc.y += a * v.y; acc.z += a * v.z; acc.w += a * v.w;
    }
    float4 b = *(const float4*)(bias + c);
    acc.x = fmaxf(acc.x + b.x, 0.f);
    acc.y = fmaxf(acc.y + b.y, 0.f);
    acc.z = fmaxf(acc.z + b.z, 0.f);
    acc.w = fmaxf(acc.w + b.w, 0.f);
    *(float4*)(g_h + (size_t)d * DCAT + c) = acc;
}

// ---------------- head: h3 = h64 @ W2 + b2, plus sq ------------------------
__global__ __launch_bounds__(256)
void head_kernel(const float* __restrict__ W2, const float* __restrict__ b2)
{
    int n = blockIdx.x * blockDim.x + threadIdx.x;
    if (n >= NNODE) return;
    float a0 = b2[0], a1 = b2[1], a2 = b2[2];
    const float* row = g_h64 + (size_t)n * 64;
#pragma unroll 8
    for (int k = 0; k < 64; k++) {
        float v = row[k];
        a0 = fmaf(v, W2[k * 3 + 0], a0);
        a1 = fmaf(v, W2[k * 3 + 1], a1);
        a2 = fmaf(v, W2[k * 3 + 2], a2);
    }
    float sq = fmaf(a2, a2, fmaf(a1, a1, a0 * a0));
    g_hp[n] = make_float4(a0, a1, a2, sq);
}

// ---------------- cdist: out[i][j] = ||h_i - h_j||, 4 j per thread ---------
__global__ __launch_bounds__(256)
void cdist_kernel(float* __restrict__ out)
{
    int j = (blockIdx.x * 256 + threadIdx.x) * 4;    // 0..16380
    int i = blockIdx.y;
    float4 hi = g_hp[i];
    float4 r;
    // dot uses the exact fmaf chain used for sq => diagonal is exactly 0
    {
        float4 hj = g_hp[j + 0];
        float dot = fmaf(hi.z, hj.z, fmaf(hi.y, hj.y, hi.x * hj.x));
        float d2 = fmaxf((hi.w + hj.w) - 2.f * dot, 0.f);
        r.x = (d2 > 0.f) ? sqrtf(d2) : 0.f;
    }
    {
        float4 hj = g_hp[j + 1];
        float dot = fmaf(hi.z, hj.z, fmaf(hi.y, hj.y, hi.x * hj.x));
        float d2 = fmaxf((hi.w + hj.w) - 2.f * dot, 0.f);
        r.y = (d2 > 0.f) ? sqrtf(d2) : 0.f;
    }
    {
        float4 hj = g_hp[j + 2];
        float dot = fmaf(hi.z, hj.z, fmaf(hi.y, hj.y, hi.x * hj.x));
        float d2 = fmaxf((hi.w + hj.w) - 2.f * dot, 0.f);
        r.z = (d2 > 0.f) ? sqrtf(d2) : 0.f;
    }
    {
        float4 hj = g_hp[j + 3];
        float dot = fmaf(hi.z, hj.z, fmaf(hi.y, hj.y, hi.x * hj.x));
        float d2 = fmaxf((hi.w + hj.w) - 2.f * dot, 0.f);
        r.w = (d2 > 0.f) ? sqrtf(d2) : 0.f;
    }
    *(float4*)&out[(size_t)i * NNODE + j] = r;
}

// ---------------------------------------------------------------------------
extern "C" void kernel_launch(void* const* d_in, const int* in_sizes, int n_in,
                              void* d_out, int out_size)
{
    const float* x       = (const float*)d_in[0];
    const int*   ei      = (const int*)d_in[1];      // int32 (JAX default)
    const float* W       = (const float*)d_in[2];
    const float* att_src = (const float*)d_in[3];
    const float* att_dst = (const float*)d_in[4];
    const float* bias    = (const float*)d_in[5];
    const float* Wa      = (const float*)d_in[6];
    const float* ba      = (const float*)d_in[7];
    const float* W1      = (const float*)d_in[8];
    const float* b1      = (const float*)d_in[9];
    const float* W2      = (const float*)d_in[10];
    const float* b2      = (const float*)d_in[11];
    float* out = (float*)d_out;

    int E = in_sizes[1] / 2;
    int Etot = E + NNODE;

    // 1) xh = x @ W   [16384,1024] K=512  (tf32, cp.async double-buffered)
    tf32gemm<0, false><<<dim3(DCAT / 64, NNODE / 128), 256>>>(
        NNODE, DCAT, 512, x, W, nullptr);

    // 2) attention scores
    attn_scores<<<NNODE, 128>>>(att_src, att_dst);

    // 3) zero z/deg
    zero_init_kernel<<<(NNODE * 2 + 255) / 256, 256>>>();

    // 4) softmax denominator + degree histogram
    edge_pass1<<<(Etot + 255) / 256, 256>>>(ei, E, Etot);

    // 5) scan degrees -> rowptr/cursor
    scan_kernel<<<1, 512>>>();

    // 6) scatter CSR (src, alpha)
    edge_scatter<<<(Etot + 255) / 256, 256>>>(ei, E, Etot);

    // 7) aggregate messages (atomic-free) + bias + relu -> h
    aggregate_kernel<<<NNODE, 256>>>(bias);

    // 8) h128 = relu(h @ Wa + ba)   K=1024, N=128
    tf32gemm<1, true><<<dim3(2, NNODE / 128), 256>>>(
        NNODE, 128, DCAT, nullptr, Wa, ba);

    // 9) h64 = relu(h128 @ W1 + b1)  K=128, N=64
    tf32gemm<2, true><<<dim3(1, NNODE / 128), 256>>>(
        NNODE, 64, 128, nullptr, W1, b1);

    // 10) h3 + sq
    head_kernel<<<NNODE / 256, 256>>>(W2, b2);

    // 11) cdist (float4 stores)
    cdist_kernel<<<dim3(NNODE / 1024, NNODE), 256>>>(out);

    (void)n_in; (void)out_size;
}

// round 9
// speedup vs baseline: 1.1239x; 1.0809x over previous
#include <cuda_runtime.h>
#include <cuda_fp16.h>
#include <math.h>
#include <stdint.h>

#define NNODE 16384
#define DCAT  1024
#define DHEAD 512
#define MAXE  (524288 + NNODE)

// ---------------- scratch (device globals; allocation-free contract) -------
__device__ __half g_xh[NNODE * DCAT];     // x @ W, fp16 (gather-friendly)
__device__ float  g_h[NNODE * DCAT];      // aggregated + bias + relu
__device__ float  g_h128[NNODE * 128];
__device__ float  g_h64[NNODE * 64];
__device__ float4 g_hp[NNODE];            // (h3.x, h3.y, h3.z, sq)
__device__ float  g_asrc[NNODE * 2];
__device__ float  g_adst[NNODE * 2];
__device__ float  g_z[NNODE * 2];
__device__ int    g_deg[NNODE];
__device__ int    g_cursor[NNODE];
__device__ int    g_rowptr[NNODE + 1];
__device__ int    g_csr_src[MAXE];
__device__ float2 g_csr_alpha[MAXE];

// ---------------- tf32 helpers ---------------------------------------------
__device__ __forceinline__ uint32_t f2tf32(float f)
{
    uint32_t u;
    asm("cvt.rna.tf32.f32 %0, %1;" : "=r"(u) : "f"(f));
    return u;
}

__device__ __forceinline__ float4 cvt4(float4 v)
{
    float4 w;
    w.x = __uint_as_float(f2tf32(v.x));
    w.y = __uint_as_float(f2tf32(v.y));
    w.z = __uint_as_float(f2tf32(v.z));
    w.w = __uint_as_float(f2tf32(v.w));
    return w;
}

__device__ __forceinline__ void mma_tf32(float& c0, float& c1, float& c2, float& c3,
                                         uint32_t a0, uint32_t a1, uint32_t a2, uint32_t a3,
                                         uint32_t b0, uint32_t b1)
{
    asm volatile(
        "mma.sync.aligned.m16n8k8.row.col.f32.tf32.tf32.f32 "
        "{%0,%1,%2,%3}, {%4,%5,%6,%7}, {%8,%9}, {%0,%1,%2,%3};"
        : "+f"(c0), "+f"(c1), "+f"(c2), "+f"(c3)
        : "r"(a0), "r"(a1), "r"(a2), "r"(a3), "r"(b0), "r"(b1));
}

// ---------------- tf32 tensor-core GEMM (R5 mainloop, known-best) ----------
// C = A[M,K] @ B[K,N] (+bias)(+relu). BM=128, BN=64, BK=16, 256 threads =
// 8 warps (4 m x 2 n), 32x32 per warp. M%128==0, N%64==0, K%16==0.
// MODE selects A/C from device globals at compile time:
//   MODE 0: A = Aarg (input x), C = g_xh  (fp16 output)
//   MODE 1: A = g_h,            C = g_h128
//   MODE 2: A = g_h128,         C = g_h64
template <int MODE, bool RELU>
__global__ __launch_bounds__(256)
void tf32gemm(int M, int N, int K,
              const float* __restrict__ Aarg, const float* __restrict__ B,
              const float* __restrict__ bias)
{
    const float* __restrict__ A =
        (MODE == 0) ? Aarg : (MODE == 1) ? (const float*)g_h : (const float*)g_h128;
    float* __restrict__ Cf =
        (MODE == 1) ? (float*)g_h128 : (float*)g_h64;

    constexpr int BM = 128, BN = 64, BK = 16;
    __shared__ float Am[BM][BK + 4];   // m-major, stride 20 (conflict-free frag LDS)
    __shared__ float Bs[BK][BN + 8];   // k-major, stride 72 (conflict-free frag LDS)

    const int tid   = threadIdx.x;
    const int lane  = tid & 31;
    const int wid   = tid >> 5;
    const int g     = lane >> 2;       // 0..7
    const int tig   = lane & 3;        // 0..3
    const int warpM = wid & 3;         // 0..3  (32 rows each)
    const int warpN = wid >> 2;        // 0..1  (32 cols each)
    const int m0    = blockIdx.y * BM;
    const int n0    = blockIdx.x * BN;

    float c[2][4][4];
#pragma unroll
    for (int mt = 0; mt < 2; mt++)
#pragma unroll
        for (int nt = 0; nt < 4; nt++)
#pragma unroll
            for (int i = 0; i < 4; i++) c[mt][nt][i] = 0.f;

    const int aRow = tid >> 2;         // 0..63
    const int aK   = (tid & 3) * 4;    // 0,4,8,12
    const int bK   = tid >> 4;         // 0..15
    const int bN   = (tid & 15) * 4;   // 0..60

    const float* Aptr = A + (size_t)(m0 + aRow) * K + aK;
    const float* Bptr = B + (size_t)bK * N + n0 + bN;

    for (int k0 = 0; k0 < K; k0 += BK) {
        *(float4*)&Am[aRow][aK]      = cvt4(*(const float4*)(Aptr + k0));
        *(float4*)&Am[64 + aRow][aK] = cvt4(*(const float4*)(Aptr + (size_t)64 * K + k0));
        *(float4*)&Bs[bK][bN]        = cvt4(*(const float4*)(Bptr + (size_t)k0 * N));
        __syncthreads();

#pragma unroll
        for (int kk = 0; kk < BK; kk += 8) {
            uint32_t a[2][4];
#pragma unroll
            for (int mt = 0; mt < 2; mt++) {
                int mm = warpM * 32 + mt * 16 + g;
                a[mt][0] = __float_as_uint(Am[mm][kk + tig]);
                a[mt][1] = __float_as_uint(Am[mm + 8][kk + tig]);
                a[mt][2] = __float_as_uint(Am[mm][kk + tig + 4]);
                a[mt][3] = __float_as_uint(Am[mm + 8][kk + tig + 4]);
            }
            uint32_t b[4][2];
#pragma unroll
            for (int nt = 0; nt < 4; nt++) {
                int nn = warpN * 32 + nt * 8 + g;
                b[nt][0] = __float_as_uint(Bs[kk + tig][nn]);
                b[nt][1] = __float_as_uint(Bs[kk + tig + 4][nn]);
            }
#pragma unroll
            for (int mt = 0; mt < 2; mt++)
#pragma unroll
                for (int nt = 0; nt < 4; nt++)
                    mma_tf32(c[mt][nt][0], c[mt][nt][1], c[mt][nt][2], c[mt][nt][3],
                             a[mt][0], a[mt][1], a[mt][2], a[mt][3],
                             b[nt][0], b[nt][1]);
        }
        __syncthreads();
    }

    // --- epilogue ---
#pragma unroll
    for (int mt = 0; mt < 2; mt++) {
        int r0 = m0 + warpM * 32 + mt * 16 + g;
#pragma unroll
        for (int nt = 0; nt < 4; nt++) {
            int cc = n0 + warpN * 32 + nt * 8 + 2 * tig;
            float b0 = 0.f, b1 = 0.f;
            if (bias) { b0 = bias[cc]; b1 = bias[cc + 1]; }
            float v00 = c[mt][nt][0] + b0, v01 = c[mt][nt][1] + b1;
            float v10 = c[mt][nt][2] + b0, v11 = c[mt][nt][3] + b1;
            if (RELU) {
                v00 = fmaxf(v00, 0.f); v01 = fmaxf(v01, 0.f);
                v10 = fmaxf(v10, 0.f); v11 = fmaxf(v11, 0.f);
            }
            if (MODE == 0) {
                // fp16 output into g_xh
                *(__half2*)&g_xh[(size_t)r0 * N + cc]       = __floats2half2_rn(v00, v01);
                *(__half2*)&g_xh[(size_t)(r0 + 8) * N + cc] = __floats2half2_rn(v10, v11);
            } else {
                *(float2*)&Cf[(size_t)r0 * N + cc]       = make_float2(v00, v01);
                *(float2*)&Cf[(size_t)(r0 + 8) * N + cc] = make_float2(v10, v11);
            }
        }
    }
}

// ---------------- attention scores: a_src/a_dst [N,2], fp16 xh -------------
__global__ __launch_bounds__(128)
void attn_scores(const float* __restrict__ att_src,
                 const float* __restrict__ att_dst)
{
    int n = blockIdx.x;
    int w = threadIdx.x >> 5;      // 0..3
    int lane = threadIdx.x & 31;
    int h = w & 1;
    const __half2* row = (const __half2*)(g_xh + (size_t)n * DCAT + h * DHEAD);
    const float* att = ((w < 2) ? att_src : att_dst) + h * DHEAD;
    float s = 0.f;
    for (int i = lane; i < DHEAD / 2; i += 32) {
        float2 p = __half22float2(row[i]);
        s += p.x * att[2 * i] + p.y * att[2 * i + 1];
    }
#pragma unroll
    for (int o = 16; o > 0; o >>= 1) s += __shfl_down_sync(0xffffffffu, s, o);
    if (lane == 0) {
        float* out = (w < 2) ? g_asrc : g_adst;
        out[n * 2 + h] = s;
    }
}

// ---------------- zero init (z, deg) ---------------------------------------
__global__ void zero_init_kernel()
{
    int i = blockIdx.x * blockDim.x + threadIdx.x;
    if (i < NNODE * 2) g_z[i] = 0.f;
    if (i < NNODE) g_deg[i] = 0;
}

__device__ __forceinline__ float leaky(float x) { return x > 0.f ? x : 0.2f * x; }

// edge_index is int32; mask is a no-op on valid data but converts surprises
// into wrong values instead of device traps.
__device__ __forceinline__ void edge_sd(const int* __restrict__ ei, int e,
                                        int E, int& s, int& d)
{
    if (e < E) {
        s = ei[e] & (NNODE - 1);
        d = ei[E + e] & (NNODE - 1);
    } else {
        s = d = e - E;   // self-loop
    }
}

// ---------------- edge pass 1: softmax denominator + degree ----------------
__global__ __launch_bounds__(256)
void edge_pass1(const int* __restrict__ ei, int E, int Etot)
{
    int e = blockIdx.x * blockDim.x + threadIdx.x;
    if (e >= Etot) return;
    int s, d;
    edge_sd(ei, e, E, s, d);
#pragma unroll
    for (int h = 0; h < 2; h++) {
        float l = leaky(g_asrc[2 * s + h] + g_adst[2 * d + h]);
        atomicAdd(&g_z[2 * d + h], expf(l));
    }
    atomicAdd(&g_deg[d], 1);
}

// ---------------- exclusive scan of degrees --> rowptr, cursor -------------
__global__ __launch_bounds__(512)
void scan_kernel()
{
    __shared__ int sums[512];
    int t = threadIdx.x;
    int base = t * 32;
    int local[32];
    int s = 0;
#pragma unroll
    for (int i = 0; i < 32; i++) { local[i] = s; s += g_deg[base + i]; }
    sums[t] = s;
    __syncthreads();
    for (int off = 1; off < 512; off <<= 1) {
        int v = (t >= off) ? sums[t - off] : 0;
        __syncthreads();
        if (t >= off) sums[t] += v;
        __syncthreads();
    }
    int prefix = (t == 0) ? 0 : sums[t - 1];
#pragma unroll
    for (int i = 0; i < 32; i++) {
        g_rowptr[base + i] = prefix + local[i];
        g_cursor[base + i] = prefix + local[i];
    }
    if (t == 511) g_rowptr[NNODE] = sums[511];
}

// ---------------- edge pass 2: scatter CSR entries (src, alpha) ------------
__global__ __launch_bounds__(256)
void edge_scatter(const int* __restrict__ ei, int E, int Etot)
{
    int e = blockIdx.x * blockDim.x + threadIdx.x;
    if (e >= Etot) return;
    int s, d;
    edge_sd(ei, e, E, s, d);
    int pos = atomicAdd(&g_cursor[d], 1);
    float2 al;
    {
        float l0 = leaky(g_asrc[2 * s + 0] + g_adst[2 * d + 0]);
        float l1 = leaky(g_asrc[2 * s + 1] + g_adst[2 * d + 1]);
        al.x = expf(l0) / fmaxf(g_z[2 * d + 0], 1e-16f);
        al.y = expf(l1) / fmaxf(g_z[2 * d + 1], 1e-16f);
    }
    g_csr_src[pos] = s;
    g_csr_alpha[pos] = al;
}

// ---------------- aggregation (atomic-free, fp16 gather) + bias + relu -----
// 128 threads, 8 columns per thread (uint4 = 8 halves per edge per thread).
__global__ __launch_bounds__(128)
void aggregate_kernel(const float* __restrict__ bias)
{
    int d = blockIdx.x;
    int c = threadIdx.x * 8;             // 0..1016
    bool head1 = (c >= DHEAD);
    int beg = g_rowptr[d], end = g_rowptr[d + 1];
    float acc[8];
#pragma unroll
    for (int k = 0; k < 8; k++) acc[k] = 0.f;

    for (int i = beg; i < end; i++) {
        int s = g_csr_src[i];
        float2 al = g_csr_alpha[i];
        float a = head1 ? al.y : al.x;
        uint4 v = *(const uint4*)(g_xh + (size_t)s * DCAT + c);
        float2 p0 = __half22float2(*(__half2*)&v.x);
        float2 p1 = __half22float2(*(__half2*)&v.y);
        float2 p2 = __half22float2(*(__half2*)&v.z);
        float2 p3 = __half22float2(*(__half2*)&v.w);
        acc[0] = fmaf(a, p0.x, acc[0]); acc[1] = fmaf(a, p0.y, acc[1]);
        acc[2] = fmaf(a, p1.x, acc[2]); acc[3] = fmaf(a, p1.y, acc[3]);
        acc[4] = fmaf(a, p2.x, acc[4]); acc[5] = fmaf(a, p2.y, acc[5]);
        acc[6] = fmaf(a, p3.x, acc[6]); acc[7] = fmaf(a, p3.y, acc[7]);
    }

    float4 b0 = *(const float4*)(bias + c);
    float4 b1 = *(const float4*)(bias + c + 4);
    float4 o0, o1;
    o0.x = fmaxf(acc[0] + b0.x, 0.f); o0.y = fmaxf(acc[1] + b0.y, 0.f);
    o0.z = fmaxf(acc[2] + b0.z, 0.f); o0.w = fmaxf(acc[3] + b0.w, 0.f);
    o1.x = fmaxf(acc[4] + b1.x, 0.f); o1.y = fmaxf(acc[5] + b1.y, 0.f);
    o1.z = fmaxf(acc[6] + b1.z, 0.f); o1.w = fmaxf(acc[7] + b1.w, 0.f);
    *(float4*)(g_h + (size_t)d * DCAT + c)     = o0;
    *(float4*)(g_h + (size_t)d * DCAT + c + 4) = o1;
}

// ---------------- head: h3 = h64 @ W2 + b2, plus sq ------------------------
__global__ __launch_bounds__(256)
void head_kernel(const float* __restrict__ W2, const float* __restrict__ b2)
{
    int n = blockIdx.x * blockDim.x + threadIdx.x;
    if (n >= NNODE) return;
    float a0 = b2[0], a1 = b2[1], a2 = b2[2];
    const float* row = g_h64 + (size_t)n * 64;
#pragma unroll 8
    for (int k = 0; k < 64; k++) {
        float v = row[k];
        a0 = fmaf(v, W2[k * 3 + 0], a0);
        a1 = fmaf(v, W2[k * 3 + 1], a1);
        a2 = fmaf(v, W2[k * 3 + 2], a2);
    }
    float sq = fmaf(a2, a2, fmaf(a1, a1, a0 * a0));
    g_hp[n] = make_float4(a0, a1, a2, sq);
}

// ---------------- cdist: out[i][j] = ||h_i - h_j||, 4 j per thread ---------
__global__ __launch_bounds__(256)
void cdist_kernel(float* __restrict__ out)
{
    int j = (blockIdx.x * 256 + threadIdx.x) * 4;    // 0..16380
    int i = blockIdx.y;
    float4 hi = g_hp[i];
    float4 r;
    // dot uses the exact fmaf chain used for sq => diagonal is exactly 0
    {
        float4 hj = g_hp[j + 0];
        float dot = fmaf(hi.z, hj.z, fmaf(hi.y, hj.y, hi.x * hj.x));
        float d2 = fmaxf((hi.w + hj.w) - 2.f * dot, 0.f);
        r.x = (d2 > 0.f) ? sqrtf(d2) : 0.f;
    }
    {
        float4 hj = g_hp[j + 1];
        float dot = fmaf(hi.z, hj.z, fmaf(hi.y, hj.y, hi.x * hj.x));
        float d2 = fmaxf((hi.w + hj.w) - 2.f * dot, 0.f);
        r.y = (d2 > 0.f) ? sqrtf(d2) : 0.f;
    }
    {
        float4 hj = g_hp[j + 2];
        float dot = fmaf(hi.z, hj.z, fmaf(hi.y, hj.y, hi.x * hj.x));
        float d2 = fmaxf((hi.w + hj.w) - 2.f * dot, 0.f);
        r.z = (d2 > 0.f) ? sqrtf(d2) : 0.f;
    }
    {
        float4 hj = g_hp[j + 3];
        float dot = fmaf(hi.z, hj.z, fmaf(hi.y, hj.y, hi.x * hj.x));
        float d2 = fmaxf((hi.w + hj.w) - 2.f * dot, 0.f);
        r.w = (d2 > 0.f) ? sqrtf(d2) : 0.f;
    }
    *(float4*)&out[(size_t)i * NNODE + j] = r;
}

// ---------------------------------------------------------------------------
extern "C" void kernel_launch(void* const* d_in, const int* in_sizes, int n_in,
                              void* d_out, int out_size)
{
    const float* x       = (const float*)d_in[0];
    const int*   ei      = (const int*)d_in[1];      // int32 (JAX default)
    const float* W       = (const float*)d_in[2];
    const float* att_src = (const float*)d_in[3];
    const float* att_dst = (const float*)d_in[4];
    const float* bias    = (const float*)d_in[5];
    const float* Wa      = (const float*)d_in[6];
    const float* ba      = (const float*)d_in[7];
    const float* W1      = (const float*)d_in[8];
    const float* b1      = (const float*)d_in[9];
    const float* W2      = (const float*)d_in[10];
    const float* b2      = (const float*)d_in[11];
    float* out = (float*)d_out;

    int E = in_sizes[1] / 2;
    int Etot = E + NNODE;

    // 1) xh = x @ W   [16384,1024] K=512  (tf32, fp16 output)
    tf32gemm<0, false><<<dim3(DCAT / 64, NNODE / 128), 256>>>(
        NNODE, DCAT, 512, x, W, nullptr);

    // 2) attention scores
    attn_scores<<<NNODE, 128>>>(att_src, att_dst);

    // 3) zero z/deg
    zero_init_kernel<<<(NNODE * 2 + 255) / 256, 256>>>();

    // 4) softmax denominator + degree histogram
    edge_pass1<<<(Etot + 255) / 256, 256>>>(ei, E, Etot);

    // 5) scan degrees -> rowptr/cursor
    scan_kernel<<<1, 512>>>();

    // 6) scatter CSR (src, alpha)
    edge_scatter<<<(Etot + 255) / 256, 256>>>(ei, E, Etot);

    // 7) aggregate messages (atomic-free, fp16 gather) + bias + relu -> h
    aggregate_kernel<<<NNODE, 128>>>(bias);

    // 8) h128 = relu(h @ Wa + ba)   K=1024, N=128
    tf32gemm<1, true><<<dim3(2, NNODE / 128), 256>>>(
        NNODE, 128, DCAT, nullptr, Wa, ba);

    // 9) h64 = relu(h128 @ W1 + b1)  K=128, N=64
    tf32gemm<2, true><<<dim3(1, NNODE / 128), 256>>>(
        NNODE, 64, 128, nullptr, W1, b1);

    // 10) h3 + sq
    head_kernel<<<NNODE / 256, 256>>>(W2, b2);

    // 11) cdist (float4 stores)
    cdist_kernel<<<dim3(NNODE / 1024, NNODE), 256>>>(out);

    (void)n_in; (void)out_size;
}

// round 13
// speedup vs baseline: 1.1281x; 1.0037x over previous
#include <cuda_runtime.h>
#include <cuda_fp16.h>
#include <math.h>
#include <stdint.h>

#define NNODE 16384
#define DCAT  1024
#define DHEAD 512
#define MAXE  (524288 + NNODE)

// ---------------- scratch (device globals; allocation-free contract) -------
__device__ __half g_xh[NNODE * DCAT];     // x @ W, fp16 (gather-friendly)
__device__ float  g_h[NNODE * DCAT];      // aggregated + bias + relu
__device__ float  g_h128[NNODE * 128];
__device__ float  g_h64[NNODE * 64];
__device__ float4 g_hp[NNODE];            // (h3.x, h3.y, h3.z, sq)
__device__ float  g_asrc[NNODE * 2];
__device__ float  g_adst[NNODE * 2];
__device__ int    g_deg[NNODE];
__device__ int    g_cursor[NNODE];
__device__ int    g_rowptr[NNODE + 1];
__device__ int    g_csr_src[MAXE];
__device__ float2 g_csr_e[MAXE];          // raw exp(logit) per head (unnormalized)

// ---------------- tf32 helpers ---------------------------------------------
__device__ __forceinline__ uint32_t f2tf32(float f)
{
    uint32_t u;
    asm("cvt.rna.tf32.f32 %0, %1;" : "=r"(u) : "f"(f));
    return u;
}

__device__ __forceinline__ float4 cvt4(float4 v)
{
    float4 w;
    w.x = __uint_as_float(f2tf32(v.x));
    w.y = __uint_as_float(f2tf32(v.y));
    w.z = __uint_as_float(f2tf32(v.z));
    w.w = __uint_as_float(f2tf32(v.w));
    return w;
}

__device__ __forceinline__ void mma_tf32(float& c0, float& c1, float& c2, float& c3,
                                         uint32_t a0, uint32_t a1, uint32_t a2, uint32_t a3,
                                         uint32_t b0, uint32_t b1)
{
    asm volatile(
        "mma.sync.aligned.m16n8k8.row.col.f32.tf32.tf32.f32 "
        "{%0,%1,%2,%3}, {%4,%5,%6,%7}, {%8,%9}, {%0,%1,%2,%3};"
        : "+f"(c0), "+f"(c1), "+f"(c2), "+f"(c3)
        : "r"(a0), "r"(a1), "r"(a2), "r"(a3), "r"(b0), "r"(b1));
}

// ---------------- tf32 tensor-core GEMM (R5 mainloop, known-best) ----------
// C = A[M,K] @ B[K,N] (+bias)(+relu). BM=128, BN=64, BK=16, 256 threads =
// 8 warps (4 m x 2 n), 32x32 per warp. M%128==0, N%64==0, K%16==0.
// MODE selects A/C from device globals at compile time:
//   MODE 0: A = Aarg (input x), C = g_xh  (fp16 output)
//   MODE 1: A = g_h,            C = g_h128
//   MODE 2: A = g_h128,         C = g_h64
template <int MODE, bool RELU>
__global__ __launch_bounds__(256)
void tf32gemm(int M, int N, int K,
              const float* __restrict__ Aarg, const float* __restrict__ B,
              const float* __restrict__ bias)
{
    const float* __restrict__ A =
        (MODE == 0) ? Aarg : (MODE == 1) ? (const float*)g_h : (const float*)g_h128;
    float* __restrict__ Cf =
        (MODE == 1) ? (float*)g_h128 : (float*)g_h64;

    constexpr int BM = 128, BN = 64, BK = 16;
    __shared__ float Am[BM][BK + 4];   // m-major, stride 20 (conflict-free frag LDS)
    __shared__ float Bs[BK][BN + 8];   // k-major, stride 72 (conflict-free frag LDS)

    const int tid   = threadIdx.x;
    const int lane  = tid & 31;
    const int wid   = tid >> 5;
    const int g     = lane >> 2;       // 0..7
    const int tig   = lane & 3;        // 0..3
    const int warpM = wid & 3;         // 0..3  (32 rows each)
    const int warpN = wid >> 2;        // 0..1  (32 cols each)
    const int m0    = blockIdx.y * BM;
    const int n0    = blockIdx.x * BN;

    float c[2][4][4];
#pragma unroll
    for (int mt = 0; mt < 2; mt++)
#pragma unroll
        for (int nt = 0; nt < 4; nt++)
#pragma unroll
            for (int i = 0; i < 4; i++) c[mt][nt][i] = 0.f;

    const int aRow = tid >> 2;         // 0..63
    const int aK   = (tid & 3) * 4;    // 0,4,8,12
    const int bK   = tid >> 4;         // 0..15
    const int bN   = (tid & 15) * 4;   // 0..60

    const float* Aptr = A + (size_t)(m0 + aRow) * K + aK;
    const float* Bptr = B + (size_t)bK * N + n0 + bN;

    for (int k0 = 0; k0 < K; k0 += BK) {
        *(float4*)&Am[aRow][aK]      = cvt4(*(const float4*)(Aptr + k0));
        *(float4*)&Am[64 + aRow][aK] = cvt4(*(const float4*)(Aptr + (size_t)64 * K + k0));
        *(float4*)&Bs[bK][bN]        = cvt4(*(const float4*)(Bptr + (size_t)k0 * N));
        __syncthreads();

#pragma unroll
        for (int kk = 0; kk < BK; kk += 8) {
            uint32_t a[2][4];
#pragma unroll
            for (int mt = 0; mt < 2; mt++) {
                int mm = warpM * 32 + mt * 16 + g;
                a[mt][0] = __float_as_uint(Am[mm][kk + tig]);
                a[mt][1] = __float_as_uint(Am[mm + 8][kk + tig]);
                a[mt][2] = __float_as_uint(Am[mm][kk + tig + 4]);
                a[mt][3] = __float_as_uint(Am[mm + 8][kk + tig + 4]);
            }
            uint32_t b[4][2];
#pragma unroll
            for (int nt = 0; nt < 4; nt++) {
                int nn = warpN * 32 + nt * 8 + g;
                b[nt][0] = __float_as_uint(Bs[kk + tig][nn]);
                b[nt][1] = __float_as_uint(Bs[kk + tig + 4][nn]);
            }
#pragma unroll
            for (int mt = 0; mt < 2; mt++)
#pragma unroll
                for (int nt = 0; nt < 4; nt++)
                    mma_tf32(c[mt][nt][0], c[mt][nt][1], c[mt][nt][2], c[mt][nt][3],
                             a[mt][0], a[mt][1], a[mt][2], a[mt][3],
                             b[nt][0], b[nt][1]);
        }
        __syncthreads();
    }

    // --- epilogue ---
#pragma unroll
    for (int mt = 0; mt < 2; mt++) {
        int r0 = m0 + warpM * 32 + mt * 16 + g;
#pragma unroll
        for (int nt = 0; nt < 4; nt++) {
            int cc = n0 + warpN * 32 + nt * 8 + 2 * tig;
            float b0 = 0.f, b1 = 0.f;
            if (bias) { b0 = bias[cc]; b1 = bias[cc + 1]; }
            float v00 = c[mt][nt][0] + b0, v01 = c[mt][nt][1] + b1;
            float v10 = c[mt][nt][2] + b0, v11 = c[mt][nt][3] + b1;
            if (RELU) {
                v00 = fmaxf(v00, 0.f); v01 = fmaxf(v01, 0.f);
                v10 = fmaxf(v10, 0.f); v11 = fmaxf(v11, 0.f);
            }
            if (MODE == 0) {
                *(__half2*)&g_xh[(size_t)r0 * N + cc]       = __floats2half2_rn(v00, v01);
                *(__half2*)&g_xh[(size_t)(r0 + 8) * N + cc] = __floats2half2_rn(v10, v11);
            } else {
                *(float2*)&Cf[(size_t)r0 * N + cc]       = make_float2(v00, v01);
                *(float2*)&Cf[(size_t)(r0 + 8) * N + cc] = make_float2(v10, v11);
            }
        }
    }
}

// ---------------- attention scores: a_src/a_dst [N,2], fp16 xh -------------
__global__ __launch_bounds__(128)
void attn_scores(const float* __restrict__ att_src,
                 const float* __restrict__ att_dst)
{
    int n = blockIdx.x;
    int w = threadIdx.x >> 5;      // 0..3
    int lane = threadIdx.x & 31;
    int h = w & 1;
    const __half2* row = (const __half2*)(g_xh + (size_t)n * DCAT + h * DHEAD);
    const float* att = ((w < 2) ? att_src : att_dst) + h * DHEAD;
    float s = 0.f;
    for (int i = lane; i < DHEAD / 2; i += 32) {
        float2 p = __half22float2(row[i]);
        s += p.x * att[2 * i] + p.y * att[2 * i + 1];
    }
#pragma unroll
    for (int o = 16; o > 0; o >>= 1) s += __shfl_down_sync(0xffffffffu, s, o);
    if (lane == 0) {
        float* out = (w < 2) ? g_asrc : g_adst;
        out[n * 2 + h] = s;
    }
}

// ---------------- zero init (deg) ------------------------------------------
__global__ void zero_init_kernel()
{
    int i = blockIdx.x * blockDim.x + threadIdx.x;
    if (i < NNODE) g_deg[i] = 0;
}

__device__ __forceinline__ float leaky(float x) { return x > 0.f ? x : 0.2f * x; }

// edge_index is int32; mask is a no-op on valid data but converts surprises
// into wrong values instead of device traps.
__device__ __forceinline__ void edge_sd(const int* __restrict__ ei, int e,
                                        int E, int& s, int& d)
{
    if (e < E) {
        s = ei[e] & (NNODE - 1);
        d = ei[E + e] & (NNODE - 1);
    } else {
        s = d = e - E;   // self-loop
    }
}

// ---------------- edge pass 1: degree histogram only -----------------------
__global__ __launch_bounds__(256)
void edge_pass1(const int* __restrict__ ei, int E, int Etot)
{
    int e = blockIdx.x * blockDim.x + threadIdx.x;
    if (e >= Etot) return;
    int s, d;
    edge_sd(ei, e, E, s, d);
    atomicAdd(&g_deg[d], 1);
}

// ---------------- exclusive scan of degrees --> rowptr, cursor -------------
__global__ __launch_bounds__(512)
void scan_kernel()
{
    __shared__ int sums[512];
    int t = threadIdx.x;
    int base = t * 32;
    int local[32];
    int s = 0;
#pragma unroll
    for (int i = 0; i < 32; i++) { local[i] = s; s += g_deg[base + i]; }
    sums[t] = s;
    __syncthreads();
    for (int off = 1; off < 512; off <<= 1) {
        int v = (t >= off) ? sums[t - off] : 0;
        __syncthreads();
        if (t >= off) sums[t] += v;
        __syncthreads();
    }
    int prefix = (t == 0) ? 0 : sums[t - 1];
#pragma unroll
    for (int i = 0; i < 32; i++) {
        g_rowptr[base + i] = prefix + local[i];
        g_cursor[base + i] = prefix + local[i];
    }
    if (t == 511) g_rowptr[NNODE] = sums[511];
}

// ---------------- edge pass 2: scatter CSR entries (src, exp) --------------
// Stores UNNORMALIZED exp(logit); normalization folded into aggregate
// (softmax denominator is linear: sum(e/z * xh) == (sum e*xh)/z).
__global__ __launch_bounds__(256)
void edge_scatter(const int* __restrict__ ei, int E, int Etot)
{
    int e = blockIdx.x * blockDim.x + threadIdx.x;
    if (e >= Etot) return;
    int s, d;
    edge_sd(ei, e, E, s, d);
    int pos = atomicAdd(&g_cursor[d], 1);
    float2 ex;
    ex.x = expf(leaky(g_asrc[2 * s + 0] + g_adst[2 * d + 0]));
    ex.y = expf(leaky(g_asrc[2 * s + 1] + g_adst[2 * d + 1]));
    g_csr_src[pos] = s;
    g_csr_e[pos] = ex;
}

// ---------------- aggregation: MLP-4 gathers + fused softmax norm ----------
// 128 threads, 8 columns per thread. Processes 4 edges per iteration with
// all index loads and gathers batched before the FMAs (4 gathers in flight).
__global__ __launch_bounds__(128)
void aggregate_kernel(const float* __restrict__ bias)
{
    int d = blockIdx.x;
    int c = threadIdx.x * 8;             // 0..1016
    bool head1 = (c >= DHEAD);
    int beg = g_rowptr[d], end = g_rowptr[d + 1];
    float acc[8];
#pragma unroll
    for (int k = 0; k < 8; k++) acc[k] = 0.f;
    float z = 0.f;                       // per-head softmax denominator

    const __half* xh = g_xh;
    int i = beg;
    for (; i + 4 <= end; i += 4) {
        int s0 = g_csr_src[i + 0], s1 = g_csr_src[i + 1];
        int s2 = g_csr_src[i + 2], s3 = g_csr_src[i + 3];
        float2 e0 = g_csr_e[i + 0], e1 = g_csr_e[i + 1];
        float2 e2 = g_csr_e[i + 2], e3 = g_csr_e[i + 3];
        uint4 v0 = *(const uint4*)(xh + (size_t)s0 * DCAT + c);
        uint4 v1 = *(const uint4*)(xh + (size_t)s1 * DCAT + c);
        uint4 v2 = *(const uint4*)(xh + (size_t)s2 * DCAT + c);
        uint4 v3 = *(const uint4*)(xh + (size_t)s3 * DCAT + c);
        float a0 = head1 ? e0.y : e0.x;
        float a1 = head1 ? e1.y : e1.x;
        float a2 = head1 ? e2.y : e2.x;
        float a3 = head1 ? e3.y : e3.x;
        z += (a0 + a1) + (a2 + a3);
#pragma unroll
        for (int q = 0; q < 4; q++) {
            uint32_t u0 = (&v0.x)[q], u1 = (&v1.x)[q], u2 = (&v2.x)[q], u3 = (&v3.x)[q];
            float2 p0 = __half22float2(*(__half2*)&u0);
            float2 p1 = __half22float2(*(__half2*)&u1);
            float2 p2 = __half22float2(*(__half2*)&u2);
            float2 p3 = __half22float2(*(__half2*)&u3);
            acc[2 * q + 0] = fmaf(a0, p0.x, fmaf(a1, p1.x, fmaf(a2, p2.x, fmaf(a3, p3.x, acc[2 * q + 0]))));
            acc[2 * q + 1] = fmaf(a0, p0.y, fmaf(a1, p1.y, fmaf(a2, p2.y, fmaf(a3, p3.y, acc[2 * q + 1]))));
        }
    }
    for (; i < end; i++) {
        int s = g_csr_src[i];
        float2 e = g_csr_e[i];
        float a = head1 ? e.y : e.x;
        z += a;
        uint4 v = *(const uint4*)(xh + (size_t)s * DCAT + c);
#pragma unroll
        for (int q = 0; q < 4; q++) {
            uint32_t u = (&v.x)[q];
            float2 p = __half22float2(*(__half2*)&u);
            acc[2 * q + 0] = fmaf(a, p.x, acc[2 * q + 0]);
            acc[2 * q + 1] = fmaf(a, p.y, acc[2 * q + 1]);
        }
    }

    float inv = 1.f / fmaxf(z, 1e-16f);
    float4 b0 = *(const float4*)(bias + c);
    float4 b1 = *(const float4*)(bias + c + 4);
    float4 o0, o1;
    o0.x = fmaxf(fmaf(acc[0], inv, b0.x), 0.f);
    o0.y = fmaxf(fmaf(acc[1], inv, b0.y), 0.f);
    o0.z = fmaxf(fmaf(acc[2], inv, b0.z), 0.f);
    o0.w = fmaxf(fmaf(acc[3], inv, b0.w), 0.f);
    o1.x = fmaxf(fmaf(acc[4], inv, b1.x), 0.f);
    o1.y = fmaxf(fmaf(acc[5], inv, b1.y), 0.f);
    o1.z = fmaxf(fmaf(acc[6], inv, b1.z), 0.f);
    o1.w = fmaxf(fmaf(acc[7], inv, b1.w), 0.f);
    *(float4*)(g_h + (size_t)d * DCAT + c)     = o0;
    *(float4*)(g_h + (size_t)d * DCAT + c + 4) = o1;
}

// ---------------- head: h3 = h64 @ W2 + b2, plus sq ------------------------
__global__ __launch_bounds__(256)
void head_kernel(const float* __restrict__ W2, const float* __restrict__ b2)
{
    int n = blockIdx.x * blockDim.x + threadIdx.x;
    if (n >= NNODE) return;
    float a0 = b2[0], a1 = b2[1], a2 = b2[2];
    const float* row = g_h64 + (size_t)n * 64;
#pragma unroll 8
    for (int k = 0; k < 64; k++) {
        float v = row[k];
        a0 = fmaf(v, W2[k * 3 + 0], a0);
        a1 = fmaf(v, W2[k * 3 + 1], a1);
        a2 = fmaf(v, W2[k * 3 + 2], a2);
    }
    float sq = fmaf(a2, a2, fmaf(a1, a1, a0 * a0));
    g_hp[n] = make_float4(a0, a1, a2, sq);
}

// ---------------- cdist: out[i][j] = ||h_i - h_j||, 4 j per thread ---------
__global__ __launch_bounds__(256)
void cdist_kernel(float* __restrict__ out)
{
    int j = (blockIdx.x * 256 + threadIdx.x) * 4;    // 0..16380
    int i = blockIdx.y;
    float4 hi = g_hp[i];
    float4 r;
    // dot uses the exact fmaf chain used for sq => diagonal is exactly 0
    {
        float4 hj = g_hp[j + 0];
        float dot = fmaf(hi.z, hj.z, fmaf(hi.y, hj.y, hi.x * hj.x));
        float d2 = fmaxf((hi.w + hj.w) - 2.f * dot, 0.f);
        r.x = (d2 > 0.f) ? sqrtf(d2) : 0.f;
    }
    {
        float4 hj = g_hp[j + 1];
        float dot = fmaf(hi.z, hj.z, fmaf(hi.y, hj.y, hi.x * hj.x));
        float d2 = fmaxf((hi.w + hj.w) - 2.f * dot, 0.f);
        r.y = (d2 > 0.f) ? sqrtf(d2) : 0.f;
    }
    {
        float4 hj = g_hp[j + 2];
        float dot = fmaf(hi.z, hj.z, fmaf(hi.y, hj.y, hi.x * hj.x));
        float d2 = fmaxf((hi.w + hj.w) - 2.f * dot, 0.f);
        r.z = (d2 > 0.f) ? sqrtf(d2) : 0.f;
    }
    {
        float4 hj = g_hp[j + 3];
        float dot = fmaf(hi.z, hj.z, fmaf(hi.y, hj.y, hi.x * hj.x));
        float d2 = fmaxf((hi.w + hj.w) - 2.f * dot, 0.f);
        r.w = (d2 > 0.f) ? sqrtf(d2) : 0.f;
    }
    *(float4*)&out[(size_t)i * NNODE + j] = r;
}

// ---------------------------------------------------------------------------
extern "C" void kernel_launch(void* const* d_in, const int* in_sizes, int n_in,
                              void* d_out, int out_size)
{
    const float* x       = (const float*)d_in[0];
    const int*   ei      = (const int*)d_in[1];      // int32 (JAX default)
    const float* W       = (const float*)d_in[2];
    const float* att_src = (const float*)d_in[3];
    const float* att_dst = (const float*)d_in[4];
    const float* bias    = (const float*)d_in[5];
    const float* Wa      = (const float*)d_in[6];
    const float* ba      = (const float*)d_in[7];
    const float* W1      = (const float*)d_in[8];
    const float* b1      = (const float*)d_in[9];
    const float* W2      = (const float*)d_in[10];
    const float* b2      = (const float*)d_in[11];
    float* out = (float*)d_out;

    int E = in_sizes[1] / 2;
    int Etot = E + NNODE;

    // 1) xh = x @ W   [16384,1024] K=512  (tf32, fp16 output)
    tf32gemm<0, false><<<dim3(DCAT / 64, NNODE / 128), 256>>>(
        NNODE, DCAT, 512, x, W, nullptr);

    // 2) attention scores
    attn_scores<<<NNODE, 128>>>(att_src, att_dst);

    // 3) zero deg
    zero_init_kernel<<<(NNODE + 255) / 256, 256>>>();

    // 4) degree histogram
    edge_pass1<<<(Etot + 255) / 256, 256>>>(ei, E, Etot);

    // 5) scan degrees -> rowptr/cursor
    scan_kernel<<<1, 512>>>();

    // 6) scatter CSR (src, exp)
    edge_scatter<<<(Etot + 255) / 256, 256>>>(ei, E, Etot);

    // 7) aggregate (MLP-4 gathers, fused softmax norm) + bias + relu -> h
    aggregate_kernel<<<NNODE, 128>>>(bias);

    // 8) h128 = relu(h @ Wa + ba)   K=1024, N=128
    tf32gemm<1, true><<<dim3(2, NNODE / 128), 256>>>(
        NNODE, 128, DCAT, nullptr, Wa, ba);

    // 9) h64 = relu(h128 @ W1 + b1)  K=128, N=64
    tf32gemm<2, true><<<dim3(1, NNODE / 128), 256>>>(
        NNODE, 64, 128, nullptr, W1, b1);

    // 10) h3 + sq
    head_kernel<<<NNODE / 256, 256>>>(W2, b2);

    // 11) cdist (float4 stores)
    cdist_kernel<<<dim3(NNODE / 1024, NNODE), 256>>>(out);

    (void)n_in; (void)out_size;
}